// round 7
// baseline (speedup 1.0000x reference)
#include <cuda_runtime.h>
#include <cstdint>

#define IN 8192
#define OUT 8192
#define RW 1024            // packed int32 rows (IN/8)
#define TPB 512            // 16 warps: 8 output-quads x 4 rowgroups per warp
#define OPB 32             // outputs per block
#define NRG 64             // concurrent row-groups
#define NIT (RW / NRG)     // 16 iterations per thread
#define DEPTH 4            // cp.async ring stages

// Exponent-OR dequant, 5 windows / 2 shifts per word (shifts on fma pipe):
//  sl = w*2048 (w<<11): n0 @[11:15) S=4096 | n1 @[15:19) S=256 | n2 @[19:23) S=16
//  w  (unshifted)     : n3 @[12:16) S=2048 | n4 @[16:20) S=128
//  sr = w>>9 (umulhi) : n5 @[11:15) S=4096 | n6 @[15:19) S=256 | n7 @[19:23) S=16
// x is prescaled by S on the fly; fma.rn.f32x2(x', 1+v/S) = x' + x*v.
// Sum(x') bias subtracted once at the end.
#define DQ(acc, ra, MA, rb, MB, xlo, xhi)                        \
    asm("{\n\t"                                                  \
        ".reg .b32 lo, hi;\n\t"                                  \
        ".reg .b64 v, xv;\n\t"                                   \
        "lop3.b32 lo, %1, " MA ", 0x3F800000, 0xEA;\n\t"         \
        "lop3.b32 hi, %2, " MB ", 0x3F800000, 0xEA;\n\t"         \
        "mov.b64 v, {lo, hi};\n\t"                               \
        "mov.b64 xv, {%3, %4};\n\t"                              \
        "fma.rn.f32x2 %0, xv, v, %0;\n\t"                        \
        "}"                                                      \
        : "+l"(acc) : "r"(ra), "r"(rb), "f"(xlo), "f"(xhi))

__device__ __forceinline__ void cp16(void* sdst, const void* gsrc) {
    unsigned s = (unsigned)__cvta_generic_to_shared(sdst);
    asm volatile("cp.async.cg.shared.global [%0], [%1], 16;\n" :: "r"(s), "l"(gsrc));
}
#define CP_COMMIT() asm volatile("cp.async.commit_group;\n" ::: "memory")
#define CP_WAIT3()  asm volatile("cp.async.wait_group 3;\n" ::: "memory")

__device__ __forceinline__ float acc_sum(unsigned long long a, unsigned long long b) {
    return (__uint_as_float((unsigned)(a & 0xffffffffu)) +
            __uint_as_float((unsigned)(a >> 32))) +
           (__uint_as_float((unsigned)(b & 0xffffffffu)) +
            __uint_as_float((unsigned)(b >> 32)));
}

__global__ __launch_bounds__(TPB, 2)
void qmv_kernel(const float* __restrict__ x, const int* __restrict__ qw,
                const float* __restrict__ scales, const float* __restrict__ zeros,
                const float* __restrict__ bias, float* __restrict__ out) {
    __shared__ uint4 ring[DEPTH][TPB];   // 32 KB weight staging
    __shared__ float red[NRG][OPB];      // 8 KB
    __shared__ float r2[4][OPB];
    __shared__ float rs[16], rsp[16];

    const int tid  = threadIdx.x;
    const int lane = tid & 31;
    const int w    = tid >> 5;
    const int og   = lane & 7;                 // output quad 0..7
    const int rg   = (w << 2) | (lane >> 3);   // row-group 0..63

    // ---- weight source pointer + kick off the pipeline immediately ----
    const uint4* qp = reinterpret_cast<const uint4*>(qw) +
                      (size_t)rg * (OUT / 4) + blockIdx.x * 8 + og;
    const size_t qstride = (size_t)NRG * (OUT / 4);

    #pragma unroll
    for (int s = 0; s < DEPTH - 1; s++) {
        cp16(&ring[s][tid], qp + (size_t)s * qstride);
        CP_COMMIT();
    }

    // ---- plain and prescaled x sums (k%8 scales: 4096,256,16,2048,128,4096,256,16)
    float sp = 0.f, spp = 0.f;
    const float4* xg = reinterpret_cast<const float4*>(x);
    #pragma unroll
    for (int i = tid; i < IN / 4; i += TPB) {
        float4 v = xg[i];
        sp += (v.x + v.y) + (v.z + v.w);
        float p0, p1, p2, p3;
        if (i & 1) {  // k%8 = 4..7
            p0 = v.x * 128.f;  p1 = v.y * 4096.f;
            p2 = v.z * 256.f;  p3 = v.w * 16.f;
        } else {      // k%8 = 0..3
            p0 = v.x * 4096.f; p1 = v.y * 256.f;
            p2 = v.z * 16.f;   p3 = v.w * 2048.f;
        }
        spp += (p0 + p1) + (p2 + p3);
    }
    #pragma unroll
    for (int o = 16; o > 0; o >>= 1) {
        sp  += __shfl_down_sync(0xffffffffu, sp, o);
        spp += __shfl_down_sync(0xffffffffu, spp, o);
    }
    if (lane == 0) { rs[w] = sp; rsp[w] = spp; }

    // ---- main loop: lane owns 4 outputs; weights from ring, x from L1 ----
    unsigned long long a0A = 0, a0B = 0, a1A = 0, a1B = 0;
    unsigned long long a2A = 0, a2B = 0, a3A = 0, a3B = 0;

    #pragma unroll 4
    for (int i = 0; i < NIT; i++) {
        if (i + DEPTH - 1 < NIT)
            cp16(&ring[(i + DEPTH - 1) & (DEPTH - 1)][tid],
                 qp + (size_t)(i + DEPTH - 1) * qstride);
        CP_COMMIT();
        CP_WAIT3();
        uint4 wv = ring[i & (DEPTH - 1)][tid];

        int r = rg + (i << 6);
        float4 xa = __ldg(xg + 2 * r);       // k0..k3
        float4 xb = __ldg(xg + 2 * r + 1);   // k4..k7
        float p0 = xa.x * 4096.f, p1 = xa.y * 256.f;
        float p2 = xa.z * 16.f,   p3 = xa.w * 2048.f;
        float p4 = xb.x * 128.f,  p5 = xb.y * 4096.f;
        float p6 = xb.z * 256.f,  p7 = xb.w * 16.f;

        unsigned sl, sr;
        // word 0 -> output o+0
        sl = wv.x * 2048u; sr = __umulhi(wv.x, 1u << 23);
        DQ(a0A, sl, "0x00007800", sl, "0x00078000", p0, p1);   // n0,n1
        DQ(a0A, sl, "0x00780000", wv.x, "0x0000F000", p2, p3); // n2,n3
        DQ(a0B, wv.x, "0x000F0000", sr, "0x00007800", p4, p5); // n4,n5
        DQ(a0B, sr, "0x00078000", sr, "0x00780000", p6, p7);   // n6,n7
        // word 1 -> output o+1
        sl = wv.y * 2048u; sr = __umulhi(wv.y, 1u << 23);
        DQ(a1A, sl, "0x00007800", sl, "0x00078000", p0, p1);
        DQ(a1A, sl, "0x00780000", wv.y, "0x0000F000", p2, p3);
        DQ(a1B, wv.y, "0x000F0000", sr, "0x00007800", p4, p5);
        DQ(a1B, sr, "0x00078000", sr, "0x00780000", p6, p7);
        // word 2 -> output o+2
        sl = wv.z * 2048u; sr = __umulhi(wv.z, 1u << 23);
        DQ(a2A, sl, "0x00007800", sl, "0x00078000", p0, p1);
        DQ(a2A, sl, "0x00780000", wv.z, "0x0000F000", p2, p3);
        DQ(a2B, wv.z, "0x000F0000", sr, "0x00007800", p4, p5);
        DQ(a2B, sr, "0x00078000", sr, "0x00780000", p6, p7);
        // word 3 -> output o+3
        sl = wv.w * 2048u; sr = __umulhi(wv.w, 1u << 23);
        DQ(a3A, sl, "0x00007800", sl, "0x00078000", p0, p1);
        DQ(a3A, sl, "0x00780000", wv.w, "0x0000F000", p2, p3);
        DQ(a3B, wv.w, "0x000F0000", sr, "0x00007800", p4, p5);
        DQ(a3B, sr, "0x00078000", sr, "0x00780000", p6, p7);
    }

    {
        float4 f = make_float4(acc_sum(a0A, a0B), acc_sum(a1A, a1B),
                               acc_sum(a2A, a2B), acc_sum(a3A, a3B));
        __syncthreads();   // covers rs/rsp writes; red written below
        *reinterpret_cast<float4*>(&red[rg][og * 4]) = f;
    }
    __syncthreads();

    // ---- reduce 64 row-groups per output ----
    if (tid < 128) {
        int o = tid & 31, seg = tid >> 5;
        float s = 0.f;
        #pragma unroll
        for (int j = 0; j < 16; j++) s += red[seg * 16 + j][o];
        r2[seg][o] = s;
    }
    __syncthreads();

    if (tid < OPB) {
        float dot = (r2[0][tid] + r2[1][tid]) + (r2[2][tid] + r2[3][tid]);
        float sx = 0.f, sxp = 0.f;
        #pragma unroll
        for (int i = 0; i < 16; i++) { sx += rs[i]; sxp += rsp[i]; }
        dot -= sxp;   // remove implicit-1.0 bias
        int o = blockIdx.x * OPB + tid;
        out[o] = bias[o] + scales[o] * dot - zeros[o] * sx;
    }
}

extern "C" void kernel_launch(void* const* d_in, const int* in_sizes, int n_in,
                              void* d_out, int out_size) {
    const float* x      = (const float*)d_in[0];
    const int*   qw     = (const int*)d_in[1];
    const float* scales = (const float*)d_in[2];
    const float* zeros  = (const float*)d_in[3];
    const float* bias   = (const float*)d_in[4];
    float* out = (float*)d_out;

    qmv_kernel<<<OUT / OPB, TPB>>>(x, qw, scales, zeros, bias, out);
}